// round 3
// baseline (speedup 1.0000x reference)
#include <cuda_runtime.h>
#include <cuda_bf16.h>
#include <math.h>

#define N_TOK 2309
#define N_T   2304
#define CDIM  1024
#define HEADS 16
#define DH    64
#define REG_N 5
#define SCALE 0.125f   // 64^-0.5

// ---------------- device scratch (static, no runtime alloc) ----------------
__device__ float g_qkv[(size_t)N_TOK * 3 * CDIM];   // (n, 3*1024): q|k|v per row
__device__ float g_kp [(size_t)N_TOK * CDIM];       // permuted K
__device__ float g_vp [(size_t)N_TOK * CDIM];       // permuted V
__device__ float g_attn[(size_t)N_TOK * CDIM];      // attention output (orig query order)
__device__ float g_qgn[CDIM];                       // normalized gate query per head
__device__ float g_sim[N_T];
__device__ float g_minmax[2];
__device__ int   g_perm[N_TOK];
__device__ int   g_npos[1];
__device__ unsigned char g_flag[N_T];

// ---------------- generic SGEMM: C = A(MxK) @ B(KxN) (+bias) ----------------
__global__ __launch_bounds__(256) void sgemm128(
    const float* __restrict__ A, const float* __restrict__ B,
    const float* __restrict__ bias, float* __restrict__ C,
    int M, int N, int K)
{
    __shared__ float As[8][128];
    __shared__ float Bs[8][128];
    int tid = threadIdx.x;
    int brow = blockIdx.y, bcol = blockIdx.x;
    int ty = tid / 16, tx = tid % 16;
    int aRow = tid >> 1, aCol = (tid & 1) * 4;
    int bRow = tid >> 5, bCol = (tid & 31) * 4;
    const float* Ab = A + (size_t)brow * 128 * K;
    const float* Bb = B + bcol * 128;
    int arow_g = brow * 128 + aRow;
    float acc[8][8] = {};
    float ra[8], rb[8];
    for (int k0 = 0; k0 < K; k0 += 8) {
        float4 av = make_float4(0.f, 0.f, 0.f, 0.f);
        if (arow_g < M) av = *(const float4*)(Ab + (size_t)aRow * K + k0 + aCol);
        As[aCol + 0][aRow] = av.x; As[aCol + 1][aRow] = av.y;
        As[aCol + 2][aRow] = av.z; As[aCol + 3][aRow] = av.w;
        float4 bv = *(const float4*)(Bb + (size_t)(k0 + bRow) * N + bCol);
        *(float4*)&Bs[bRow][bCol] = bv;
        __syncthreads();
#pragma unroll
        for (int kk = 0; kk < 8; kk++) {
            *(float4*)&ra[0] = *(float4*)&As[kk][ty * 8];
            *(float4*)&ra[4] = *(float4*)&As[kk][ty * 8 + 4];
            *(float4*)&rb[0] = *(float4*)&Bs[kk][tx * 8];
            *(float4*)&rb[4] = *(float4*)&Bs[kk][tx * 8 + 4];
#pragma unroll
            for (int i = 0; i < 8; i++)
#pragma unroll
                for (int j = 0; j < 8; j++)
                    acc[i][j] += ra[i] * rb[j];
        }
        __syncthreads();
    }
#pragma unroll
    for (int i = 0; i < 8; i++) {
        int r = brow * 128 + ty * 8 + i;
        if (r >= M) break;
#pragma unroll
        for (int j = 0; j < 8; j += 4) {
            int cidx = bcol * 128 + tx * 8 + j;
            float4 o;
            o.x = acc[i][j + 0]; o.y = acc[i][j + 1];
            o.z = acc[i][j + 2]; o.w = acc[i][j + 3];
            if (bias) {
                o.x += bias[cidx + 0]; o.y += bias[cidx + 1];
                o.z += bias[cidx + 2]; o.w += bias[cidx + 3];
            }
            *(float4*)(C + (size_t)r * N + cidx) = o;
        }
    }
}

// ---------------- normalize gate query g_info[0][0] per head ----------------
__global__ void qgn_kernel(const float* __restrict__ g_info)
{
    int h = threadIdx.x >> 5, lane = threadIdx.x & 31;
    float v0 = g_info[h * DH + lane];
    float v1 = g_info[h * DH + lane + 32];
    float n = v0 * v0 + v1 * v1;
#pragma unroll
    for (int o = 16; o > 0; o >>= 1) n += __shfl_xor_sync(0xffffffffu, n, o);
    float inv = 1.0f / sqrtf(n);
    g_qgn[h * DH + lane] = v0 * inv;
    g_qgn[h * DH + lane + 32] = v1 * inv;
}

// ---------------- per-token cosine similarity (mean over heads) -------------
__global__ void sim_kernel()
{
    int t = blockIdx.x;                // 0..2303
    int lane = threadIdx.x & 31, warp = threadIdx.x >> 5;
    __shared__ float wacc[4];
    const float* qrow = g_qkv + (size_t)(t + REG_N) * (3 * CDIM);
    float local = 0.f;
    for (int h = warp; h < HEADS; h += 4) {
        float q0 = qrow[h * DH + lane];
        float q1 = qrow[h * DH + lane + 32];
        float gg0 = g_qgn[h * DH + lane];
        float gg1 = g_qgn[h * DH + lane + 32];
        float d = q0 * gg0 + q1 * gg1;
        float nq = q0 * q0 + q1 * q1;
#pragma unroll
        for (int o = 16; o > 0; o >>= 1) {
            d += __shfl_xor_sync(0xffffffffu, d, o);
            nq += __shfl_xor_sync(0xffffffffu, nq, o);
        }
        if (lane == 0) local += d / sqrtf(nq);
    }
    if (lane == 0) wacc[warp] = local;
    __syncthreads();
    if (threadIdx.x == 0)
        g_sim[t] = (wacc[0] + wacc[1] + wacc[2] + wacc[3]) * (1.0f / 16.0f);
}

// ---------------- global min/max of sim ----------------
__global__ void minmax_kernel()
{
    float mn = 1e30f, mx = -1e30f;
    for (int i = threadIdx.x; i < N_T; i += 1024) {
        float v = g_sim[i];
        mn = fminf(mn, v); mx = fmaxf(mx, v);
    }
    __shared__ float smn[32], smx[32];
    int lane = threadIdx.x & 31, warp = threadIdx.x >> 5;
#pragma unroll
    for (int o = 16; o > 0; o >>= 1) {
        mn = fminf(mn, __shfl_xor_sync(0xffffffffu, mn, o));
        mx = fmaxf(mx, __shfl_xor_sync(0xffffffffu, mx, o));
    }
    if (lane == 0) { smn[warp] = mn; smx[warp] = mx; }
    __syncthreads();
    if (warp == 0) {
        mn = smn[lane]; mx = smx[lane];
#pragma unroll
        for (int o = 16; o > 0; o >>= 1) {
            mn = fminf(mn, __shfl_xor_sync(0xffffffffu, mn, o));
            mx = fmaxf(mx, __shfl_xor_sync(0xffffffffu, mx, o));
        }
        if (lane == 0) { g_minmax[0] = mn; g_minmax[1] = mx; }
    }
}

// ---------------- threshold + prefix scan -> key permutation ----------------
__global__ void mask_scan_kernel()   // blockDim = 768, each thread 3 tokens
{
    int tid = threadIdx.x;
    float mn = g_minmax[0], mx = g_minmax[1];
    float inv = 1.0f / (mx - mn);
    int t0 = tid * 3;
    int f[3]; int c = 0;
#pragma unroll
    for (int e = 0; e < 3; e++) {
        int t = t0 + e;
        int fl = ((g_sim[t] - mn) * inv > 0.9f) ? 1 : 0;
        f[e] = fl; c += fl;
        g_flag[t] = (unsigned char)fl;
    }
    int lane = tid & 31, warp = tid >> 5;
    int incl = c;
#pragma unroll
    for (int o = 1; o < 32; o <<= 1) {
        int v = __shfl_up_sync(0xffffffffu, incl, o);
        if (lane >= o) incl += v;
    }
    __shared__ int wsum[24];
    __shared__ int s_npos;
    if (lane == 31) wsum[warp] = incl;
    __syncthreads();
    if (tid == 0) {
        int acc = 0;
        for (int w = 0; w < 24; w++) { int v = wsum[w]; wsum[w] = acc; acc += v; }
        s_npos = acc;
        g_npos[0] = acc;
        for (int i = 0; i < REG_N; i++) g_perm[i] = i;
    }
    __syncthreads();
    int excl = incl - c + wsum[warp];
    int npos = s_npos;
    int pp = excl;
#pragma unroll
    for (int e = 0; e < 3; e++) {
        int t = t0 + e;
        if (f[e]) { g_perm[REG_N + pp] = t + REG_N; pp++; }
        else      { g_perm[REG_N + npos + (t - pp)] = t + REG_N; }
    }
}

// ---------------- gather permuted K/V ----------------
__global__ void gather_kernel(int /*dummy*/)
{
    int s = blockIdx.x;
    int src = g_perm[s];
    const float* kv = g_qkv + (size_t)src * (3 * CDIM);
    int off = threadIdx.x * 4;
    *(float4*)(g_kp + (size_t)s * CDIM + off) = *(const float4*)(kv + CDIM + off);
    *(float4*)(g_vp + (size_t)s * CDIM + off) = *(const float4*)(kv + 2 * CDIM + off);
}

// ---------------- flash attention with pos/neg dual accumulators ------------
#define PAD 68   // row stride (floats) for 64-wide tiles: 16B-aligned, conflict-mitigating

__device__ __forceinline__ void compute_S(const float* Qst, const float* Kst,
                                          float* St, int tq, int tk)
{
    float s[4][4] = {};
#pragma unroll 8
    for (int kk = 0; kk < 64; kk++) {
        float4 a = *(const float4*)&Qst[kk * PAD + tq * 4];
        float4 b = *(const float4*)&Kst[kk * PAD + tk * 4];
        s[0][0] += a.x * b.x; s[0][1] += a.x * b.y; s[0][2] += a.x * b.z; s[0][3] += a.x * b.w;
        s[1][0] += a.y * b.x; s[1][1] += a.y * b.y; s[1][2] += a.y * b.z; s[1][3] += a.y * b.w;
        s[2][0] += a.z * b.x; s[2][1] += a.z * b.y; s[2][2] += a.z * b.z; s[2][3] += a.z * b.w;
        s[3][0] += a.w * b.x; s[3][1] += a.w * b.y; s[3][2] += a.w * b.z; s[3][3] += a.w * b.w;
    }
#pragma unroll
    for (int j = 0; j < 4; j++)
#pragma unroll
        for (int i = 0; i < 4; i++)
            St[(tk * 4 + j) * PAD + tq * 4 + i] = s[i][j];   // St[k][q]
}

// GRP: 0 = pos (keys [0, pend)), 1 = neg (keys [0,5) U [pend, N_TOK))
template <int GRP>
__device__ __forceinline__ void softmax_pv(
    float* St, const float* Vs, float* red,
    float* s_m, float* s_l, float* s_al,
    float acc[4][4], int base, int pend, int tid)
{
    __syncthreads();    // St fully written
    int r = tid & 63, sub = tid >> 6;
    // phase 1: tile max (group-masked)
    float pm = -1e30f;
#pragma unroll
    for (int kk = sub * 16; kk < sub * 16 + 16; kk++) {
        int kidx = base + kk;
        bool in = (GRP == 0) ? (kidx < pend)
                             : ((kidx < REG_N) || (kidx >= pend && kidx < N_TOK));
        float v = St[kk * PAD + r];
        if (in) pm = fmaxf(pm, v);
    }
    red[sub * 64 + r] = pm;
    __syncthreads();
    if (tid < 64) {
        float mt = fmaxf(fmaxf(red[tid], red[64 + tid]),
                         fmaxf(red[128 + tid], red[192 + tid]));
        float mo = s_m[tid];
        float mn2 = fmaxf(mo, mt);
        s_al[tid] = __expf(mo - mn2);
        s_m[tid] = mn2;
    }
    __syncthreads();
    // phase 2: exp + row sum
    float mnv = s_m[r];
    float ps = 0.f;
#pragma unroll
    for (int kk = sub * 16; kk < sub * 16 + 16; kk++) {
        int kidx = base + kk;
        bool in = (GRP == 0) ? (kidx < pend)
                             : ((kidx < REG_N) || (kidx >= pend && kidx < N_TOK));
        float e = in ? __expf(St[kk * PAD + r] - mnv) : 0.f;
        St[kk * PAD + r] = e;
        ps += e;
    }
    red[sub * 64 + r] = ps;
    __syncthreads();
    if (tid < 64)
        s_l[tid] = s_l[tid] * s_al[tid]
                 + red[tid] + red[64 + tid] + red[128 + tid] + red[192 + tid];
    // PV
    int tq = tid >> 4, td = tid & 15;
    float al[4];
#pragma unroll
    for (int i = 0; i < 4; i++) al[i] = s_al[tq * 4 + i];
#pragma unroll
    for (int i = 0; i < 4; i++)
#pragma unroll
        for (int j = 0; j < 4; j++)
            acc[i][j] *= al[i];
#pragma unroll 4
    for (int k = 0; k < 64; k++) {
        float4 a = *(const float4*)&St[k * PAD + tq * 4];
        float4 b = *(const float4*)&Vs[k * PAD + td * 4];
        acc[0][0] += a.x * b.x; acc[0][1] += a.x * b.y; acc[0][2] += a.x * b.z; acc[0][3] += a.x * b.w;
        acc[1][0] += a.y * b.x; acc[1][1] += a.y * b.y; acc[1][2] += a.y * b.z; acc[1][3] += a.y * b.w;
        acc[2][0] += a.z * b.x; acc[2][1] += a.z * b.y; acc[2][2] += a.z * b.z; acc[2][3] += a.z * b.w;
        acc[3][0] += a.w * b.x; acc[3][1] += a.w * b.y; acc[3][2] += a.w * b.z; acc[3][3] += a.w * b.w;
    }
}

__global__ __launch_bounds__(256) void flash_kernel(int /*dummy*/)
{
    extern __shared__ float sm[];
    float* Qst = sm;                  // [64][PAD], d-major (transposed)
    float* Kst = Qst + 64 * PAD;      // [64][PAD], d-major
    float* Vs  = Kst + 64 * PAD;      // [64][PAD], k-major
    float* St  = Vs  + 64 * PAD;      // [64][PAD], k-major (S transposed)
    float* red  = St + 64 * PAD;      // [4*64]
    float* s_mp = red + 256;
    float* s_lp = s_mp + 64;
    float* s_mn = s_lp + 64;
    float* s_ln = s_mn + 64;
    float* s_al = s_ln + 64;

    int tid = threadIdx.x;
    int h = blockIdx.y, qt = blockIdx.x;
    int qbase = qt * 64;
    int pend = REG_N + g_npos[0];

    // load Q tile transposed (x scale): 64 rows x 64 dims, 4 float4 per thread
    {
        int r = tid >> 2, c0 = (tid & 3) * 16;
        int q = qbase + r;
        const float* src = g_qkv + (size_t)q * (3 * CDIM) + h * DH;
#pragma unroll
        for (int d4 = c0; d4 < c0 + 16; d4 += 4) {
            float4 qv = make_float4(0.f, 0.f, 0.f, 0.f);
            if (q < N_TOK) qv = *(const float4*)(src + d4);
            Qst[(d4 + 0) * PAD + r] = qv.x * SCALE;
            Qst[(d4 + 1) * PAD + r] = qv.y * SCALE;
            Qst[(d4 + 2) * PAD + r] = qv.z * SCALE;
            Qst[(d4 + 3) * PAD + r] = qv.w * SCALE;
        }
    }
    if (tid < 64) {
        s_mp[tid] = -1e30f; s_lp[tid] = 0.f;
        s_mn[tid] = -1e30f; s_ln[tid] = 0.f;
    }
    float accp[4][4] = {}, accn[4][4] = {};
    int tq = tid >> 4, tk = tid & 15;

    for (int base = 0; base < N_TOK; base += 64) {
        __syncthreads();
        // load K (transposed) and V tiles: 4 float4 per thread each
        {
            int r = tid >> 2, c0 = (tid & 3) * 16;
            int kidx = base + r;
            const float* ksrc = g_kp + (size_t)kidx * CDIM + h * DH;
            const float* vsrc = g_vp + (size_t)kidx * CDIM + h * DH;
#pragma unroll
            for (int d4 = c0; d4 < c0 + 16; d4 += 4) {
                float4 kv = make_float4(0.f, 0.f, 0.f, 0.f);
                float4 vv = make_float4(0.f, 0.f, 0.f, 0.f);
                if (kidx < N_TOK) {
                    kv = *(const float4*)(ksrc + d4);
                    vv = *(const float4*)(vsrc + d4);
                }
                Kst[(d4 + 0) * PAD + r] = kv.x;
                Kst[(d4 + 1) * PAD + r] = kv.y;
                Kst[(d4 + 2) * PAD + r] = kv.z;
                Kst[(d4 + 3) * PAD + r] = kv.w;
                *(float4*)&Vs[r * PAD + d4] = vv;
            }
        }
        __syncthreads();

        bool runPos = base < pend;
        bool runNeg = (base < REG_N) || (base + 64 > pend);

        compute_S(Qst, Kst, St, tq, tk);
        if (runPos)
            softmax_pv<0>(St, Vs, red, s_mp, s_lp, s_al, accp, base, pend, tid);
        if (runNeg) {
            if (runPos) { __syncthreads(); compute_S(Qst, Kst, St, tq, tk); }
            softmax_pv<1>(St, Vs, red, s_mn, s_ln, s_al, accn, base, pend, tid);
        }
    }
    __syncthreads();

    // epilogue: combine pos/neg per the reference rules
    int td = tid & 15;
    tq = tid >> 4;
#pragma unroll
    for (int i = 0; i < 4; i++) {
        int r = tq * 4 + i;
        int q = qbase + r;
        if (q >= N_TOK) continue;
        float invlp = 1.f / s_lp[r];
        float invln = 1.f / s_ln[r];
        float vals[4];
#pragma unroll
        for (int j = 0; j < 4; j++) {
            float op = accp[i][j] * invlp;
            float on = accn[i][j] * invln;
            float vv;
            if (q < REG_N) vv = 0.5f * (op + on);
            else vv = g_flag[q - REG_N] ? op : on;
            vals[j] = vv;
        }
        *(float4*)(g_attn + (size_t)q * CDIM + h * DH + td * 4) =
            make_float4(vals[0], vals[1], vals[2], vals[3]);
    }
}

// ---------------- launcher ----------------
extern "C" void kernel_launch(void* const* d_in, const int* in_sizes, int n_in,
                              void* d_out, int out_size)
{
    const float* x = nullptr; const float* ginfo = nullptr;
    const float* wqkv = nullptr; const float* wproj = nullptr;
    const float* bproj = nullptr;
    for (int i = 0; i < n_in; i++) {
        switch (in_sizes[i]) {
            case N_TOK * CDIM:      x = (const float*)d_in[i]; break;      // 2364416
            case 12 * 2 * CDIM:     ginfo = (const float*)d_in[i]; break;  // 24576
            case CDIM * 3 * CDIM:   wqkv = (const float*)d_in[i]; break;   // 3145728
            case CDIM * CDIM:       wproj = (const float*)d_in[i]; break;  // 1048576
            case CDIM:              bproj = (const float*)d_in[i]; break;  // 1024
        }
    }
    float* out = (float*)d_out;

    float* qkv;  cudaGetSymbolAddress((void**)&qkv,  g_qkv);
    float* attn; cudaGetSymbolAddress((void**)&attn, g_attn);

    // 1. QKV GEMM: (2309,1024) @ (1024,3072)
    {
        dim3 grid(3 * CDIM / 128, (N_TOK + 127) / 128);
        sgemm128<<<grid, 256>>>(x, wqkv, nullptr, qkv, N_TOK, 3 * CDIM, CDIM);
    }
    // 2. gate vector normalization
    qgn_kernel<<<1, 512>>>(ginfo);
    // 3. per-token similarity
    sim_kernel<<<N_T, 128>>>();
    // 4. min/max
    minmax_kernel<<<1, 1024>>>();
    // 5. threshold + scan -> permutation
    mask_scan_kernel<<<1, 768>>>();
    // 6. gather permuted K/V
    gather_kernel<<<N_TOK, 256>>>(0);
    // 7. flash attention (dual accumulator)
    {
        int smem = (4 * 64 * PAD + 256 + 5 * 64) * (int)sizeof(float);
        cudaFuncSetAttribute(flash_kernel,
                             cudaFuncAttributeMaxDynamicSharedMemorySize, smem);
        dim3 grid((N_TOK + 63) / 64, HEADS);
        flash_kernel<<<grid, 256, smem>>>(0);
    }
    // 8. projection GEMM: (2309,1024) @ (1024,1024) + bias
    {
        dim3 grid(CDIM / 128, (N_TOK + 127) / 128);
        sgemm128<<<grid, 256>>>(attn, wproj, bproj, out, N_TOK, CDIM, CDIM);
    }
}

// round 5
// speedup vs baseline: 1.1816x; 1.1816x over previous
#include <cuda_runtime.h>
#include <cuda_bf16.h>
#include <math.h>
#include <stdint.h>

#define N_TOK 2309
#define N_T   2304
#define CDIM  1024
#define HEADS 16
#define DH    64
#define REG_N 5
#define SCALE 0.125f   // 64^-0.5

// ---------------- device scratch (static, no runtime alloc) ----------------
__device__ float g_qkv[(size_t)N_TOK * 3 * CDIM];   // (n, 3*1024): q|k|v per row
__device__ float g_kp [(size_t)N_TOK * CDIM];       // permuted K
__device__ float g_vp [(size_t)N_TOK * CDIM];       // permuted V
__device__ float g_attn[(size_t)N_TOK * CDIM];      // attention output (orig query order)
__device__ float g_sim[N_T];
__device__ int   g_perm[N_TOK];
__device__ int   g_npos[1];
__device__ unsigned char g_flag[N_T];

// ================= warp-level tf32 MMA GEMM (3xTF32) ==========================
// C = A(MxK) @ B(KxN) (+bias).  A row-major, B row-major (k-major = what mma wants).
// CTA tile 128x128, 8 warps in 4(M) x 2(N), warp tile 32x64, K-slab 32.
// smem layout: k-major [k][m or n] with row pitch 136 floats (conflict-free frags).

#define GPITCH 136
#define SLAB   32
// float offsets inside dynamic smem
#define OFF_AH 0
#define OFF_AL (SLAB * GPITCH)
#define OFF_BH (2 * SLAB * GPITCH)
#define OFF_BL (3 * SLAB * GPITCH)
#define GEMM_SMEM_FLOATS (4 * SLAB * GPITCH)

__device__ __forceinline__ float tf32r(float v)
{
    uint32_t u;
    asm("cvt.rna.tf32.f32 %0, %1;" : "=r"(u) : "f"(v));
    return __uint_as_float(u);
}

__device__ __forceinline__ void mma_tf32(float* d, const uint32_t* a, const uint32_t* b)
{
    asm volatile(
        "mma.sync.aligned.m16n8k8.row.col.f32.tf32.tf32.f32 "
        "{%0,%1,%2,%3}, {%4,%5,%6,%7}, {%8,%9}, {%0,%1,%2,%3};"
        : "+f"(d[0]), "+f"(d[1]), "+f"(d[2]), "+f"(d[3])
        : "r"(a[0]), "r"(a[1]), "r"(a[2]), "r"(a[3]), "r"(b[0]), "r"(b[1]));
}

__global__ __launch_bounds__(256) void gemm_mma(
    const float* __restrict__ A, const float* __restrict__ B,
    const float* __restrict__ bias, float* __restrict__ C,
    int M, int N, int K)
{
    extern __shared__ float sm[];
    float* sAh = sm + OFF_AH;
    float* sAl = sm + OFF_AL;
    float* sBh = sm + OFF_BH;
    float* sBl = sm + OFF_BL;

    int tid = threadIdx.x;
    int warp = tid >> 5, lane = tid & 31;
    int g = lane >> 2, t = lane & 3;
    int mw = (warp >> 1) * 32;          // warp M offset in tile
    int nw = (warp & 1) * 64;           // warp N offset in tile
    int brow = blockIdx.y, bcol = blockIdx.x;

    // A loader: thread -> row (tid>>1), k-half (tid&1)*16
    int aRow = tid >> 1;
    int aHalf = (tid & 1) * 16;
    int aRowG = brow * 128 + aRow;
    bool aok = aRowG < M;
    const float* aptr = A + (size_t)aRowG * K + aHalf;
    // B loader: thread -> k-row (tid>>3), n-chunk (tid&7)*16
    int bK = tid >> 3;
    int bN0 = (tid & 7) * 16;
    const float* bptr = B + (size_t)bK * N + bcol * 128 + bN0;

    float c[64];
#pragma unroll
    for (int i = 0; i < 64; i++) c[i] = 0.f;

    int nslab = K / SLAB;
    for (int s = 0; s < nslab; s++) {
        if (s) __syncthreads();
        // ---- load A slab (transpose to k-major, hi/lo split) ----
#pragma unroll
        for (int j = 0; j < 4; j++) {
            float4 v = make_float4(0.f, 0.f, 0.f, 0.f);
            if (aok) v = *(const float4*)(aptr + s * SLAB + j * 4);
            int k0 = aHalf + j * 4;
            float hx = tf32r(v.x), hy = tf32r(v.y), hz = tf32r(v.z), hw = tf32r(v.w);
            sAh[(k0 + 0) * GPITCH + aRow] = hx;
            sAh[(k0 + 1) * GPITCH + aRow] = hy;
            sAh[(k0 + 2) * GPITCH + aRow] = hz;
            sAh[(k0 + 3) * GPITCH + aRow] = hw;
            sAl[(k0 + 0) * GPITCH + aRow] = tf32r(v.x - hx);
            sAl[(k0 + 1) * GPITCH + aRow] = tf32r(v.y - hy);
            sAl[(k0 + 2) * GPITCH + aRow] = tf32r(v.z - hz);
            sAl[(k0 + 3) * GPITCH + aRow] = tf32r(v.w - hw);
        }
        // ---- load B slab (already k-major, hi/lo split) ----
#pragma unroll
        for (int j = 0; j < 4; j++) {
            float4 v = *(const float4*)(bptr + (size_t)s * SLAB * N + j * 4);
            float4 hi, lo;
            hi.x = tf32r(v.x); lo.x = tf32r(v.x - hi.x);
            hi.y = tf32r(v.y); lo.y = tf32r(v.y - hi.y);
            hi.z = tf32r(v.z); lo.z = tf32r(v.z - hi.z);
            hi.w = tf32r(v.w); lo.w = tf32r(v.w - hi.w);
            *(float4*)&sBh[bK * GPITCH + bN0 + j * 4] = hi;
            *(float4*)&sBl[bK * GPITCH + bN0 + j * 4] = lo;
        }
        __syncthreads();
        // ---- compute 4 k8 steps ----
#pragma unroll
        for (int kk = 0; kk < SLAB; kk += 8) {
            uint32_t ah[2][4], al[2][4];
#pragma unroll
            for (int am = 0; am < 2; am++) {
                int m0 = mw + am * 16 + g;
#pragma unroll
                for (int rr = 0; rr < 4; rr++) {
                    int k = kk + t + ((rr >> 1) << 2);
                    int m = m0 + ((rr & 1) << 3);
                    ah[am][rr] = __float_as_uint(sAh[k * GPITCH + m]);
                    al[am][rr] = __float_as_uint(sAl[k * GPITCH + m]);
                }
            }
#pragma unroll
            for (int an = 0; an < 8; an++) {
                int n = nw + an * 8 + g;
                uint32_t bh[2], bl[2];
#pragma unroll
                for (int rr = 0; rr < 2; rr++) {
                    int k = kk + t + rr * 4;
                    bh[rr] = __float_as_uint(sBh[k * GPITCH + n]);
                    bl[rr] = __float_as_uint(sBl[k * GPITCH + n]);
                }
#pragma unroll
                for (int am = 0; am < 2; am++) {
                    float* cc = &c[(am * 8 + an) * 4];
                    mma_tf32(cc, ah[am], bh);
                    mma_tf32(cc, al[am], bh);
                    mma_tf32(cc, ah[am], bl);
                }
            }
        }
    }

    // ---- epilogue ----
#pragma unroll
    for (int am = 0; am < 2; am++) {
#pragma unroll
        for (int an = 0; an < 8; an++) {
            float* cc = &c[(am * 8 + an) * 4];
            int row0 = brow * 128 + mw + am * 16 + g;
            int col = bcol * 128 + nw + an * 8 + 2 * t;
            float bx = 0.f, by = 0.f;
            if (bias) { bx = bias[col]; by = bias[col + 1]; }
            if (row0 < M) {
                float2 o; o.x = cc[0] + bx; o.y = cc[1] + by;
                *(float2*)(C + (size_t)row0 * N + col) = o;
            }
            if (row0 + 8 < M) {
                float2 o; o.x = cc[2] + bx; o.y = cc[3] + by;
                *(float2*)(C + (size_t)(row0 + 8) * N + col) = o;
            }
        }
    }
}

// ---------------- per-token cosine similarity (gate normalized inline) ------
__global__ void sim_kernel(const float* __restrict__ g_info)
{
    int t = blockIdx.x;                // 0..2303
    int lane = threadIdx.x & 31, warp = threadIdx.x >> 5;
    __shared__ float wacc[4];
    const float* qrow = g_qkv + (size_t)(t + REG_N) * (3 * CDIM);
    float local = 0.f;
    for (int h = warp; h < HEADS; h += 4) {
        float q0 = qrow[h * DH + lane];
        float q1 = qrow[h * DH + lane + 32];
        float g0 = g_info[h * DH + lane];
        float g1 = g_info[h * DH + lane + 32];
        float d = q0 * g0 + q1 * g1;
        float nq = q0 * q0 + q1 * q1;
        float ng = g0 * g0 + g1 * g1;
#pragma unroll
        for (int o = 16; o > 0; o >>= 1) {
            d  += __shfl_xor_sync(0xffffffffu, d, o);
            nq += __shfl_xor_sync(0xffffffffu, nq, o);
            ng += __shfl_xor_sync(0xffffffffu, ng, o);
        }
        if (lane == 0) local += d / (sqrtf(nq) * sqrtf(ng));
    }
    if (lane == 0) wacc[warp] = local;
    __syncthreads();
    if (threadIdx.x == 0)
        g_sim[t] = (wacc[0] + wacc[1] + wacc[2] + wacc[3]) * (1.0f / 16.0f);
}

// ---------------- minmax + threshold + prefix scan -> key permutation -------
__global__ void maskscan_kernel()   // blockDim = 768, each thread 3 tokens
{
    int tid = threadIdx.x;
    int lane = tid & 31, warp = tid >> 5;
    int t0 = tid * 3;
    float v0 = g_sim[t0], v1 = g_sim[t0 + 1], v2 = g_sim[t0 + 2];
    float mn = fminf(v0, fminf(v1, v2));
    float mx = fmaxf(v0, fmaxf(v1, v2));
#pragma unroll
    for (int o = 16; o > 0; o >>= 1) {
        mn = fminf(mn, __shfl_xor_sync(0xffffffffu, mn, o));
        mx = fmaxf(mx, __shfl_xor_sync(0xffffffffu, mx, o));
    }
    __shared__ float smn[24], smx[24];
    __shared__ float s_bmn, s_bmx;
    if (lane == 0) { smn[warp] = mn; smx[warp] = mx; }
    __syncthreads();
    if (tid == 0) {
        float a = smn[0], b = smx[0];
        for (int w = 1; w < 24; w++) { a = fminf(a, smn[w]); b = fmaxf(b, smx[w]); }
        s_bmn = a; s_bmx = b;
    }
    __syncthreads();
    float bmn = s_bmn;
    float inv = 1.0f / (s_bmx - bmn);
    int f[3]; int c = 0;
    f[0] = ((v0 - bmn) * inv > 0.9f) ? 1 : 0;
    f[1] = ((v1 - bmn) * inv > 0.9f) ? 1 : 0;
    f[2] = ((v2 - bmn) * inv > 0.9f) ? 1 : 0;
#pragma unroll
    for (int e = 0; e < 3; e++) {
        c += f[e];
        g_flag[t0 + e] = (unsigned char)f[e];
    }
    int incl = c;
#pragma unroll
    for (int o = 1; o < 32; o <<= 1) {
        int v = __shfl_up_sync(0xffffffffu, incl, o);
        if (lane >= o) incl += v;
    }
    __shared__ int wsum[24];
    __shared__ int s_npos;
    if (lane == 31) wsum[warp] = incl;
    __syncthreads();
    if (tid == 0) {
        int acc = 0;
        for (int w = 0; w < 24; w++) { int v = wsum[w]; wsum[w] = acc; acc += v; }
        s_npos = acc;
        g_npos[0] = acc;
        for (int i = 0; i < REG_N; i++) g_perm[i] = i;
    }
    __syncthreads();
    int excl = incl - c + wsum[warp];
    int npos = s_npos;
    int pp = excl;
#pragma unroll
    for (int e = 0; e < 3; e++) {
        int t = t0 + e;
        if (f[e]) { g_perm[REG_N + pp] = t + REG_N; pp++; }
        else      { g_perm[REG_N + npos + (t - pp)] = t + REG_N; }
    }
}

// ---------------- gather permuted K / V (split for launch-index control) ----
__global__ void gatherK_kernel(int /*dummy*/)
{
    int s = blockIdx.x;
    int src = g_perm[s];
    const float* kv = g_qkv + (size_t)src * (3 * CDIM);
    int off = threadIdx.x * 4;
    *(float4*)(g_kp + (size_t)s * CDIM + off) = *(const float4*)(kv + CDIM + off);
}
__global__ void gatherV_kernel(int /*dummy*/)
{
    int s = blockIdx.x;
    int src = g_perm[s];
    const float* kv = g_qkv + (size_t)src * (3 * CDIM);
    int off = threadIdx.x * 4;
    *(float4*)(g_vp + (size_t)s * CDIM + off) = *(const float4*)(kv + 2 * CDIM + off);
}

// ---------------- flash attention with pos/neg dual accumulators ------------
#define PAD 68

__device__ __forceinline__ void compute_S(const float* Qst, const float* Kst,
                                          float* St, int tq, int tk)
{
    float s[4][4] = {};
#pragma unroll 8
    for (int kk = 0; kk < 64; kk++) {
        float4 a = *(const float4*)&Qst[kk * PAD + tq * 4];
        float4 b = *(const float4*)&Kst[kk * PAD + tk * 4];
        s[0][0] += a.x * b.x; s[0][1] += a.x * b.y; s[0][2] += a.x * b.z; s[0][3] += a.x * b.w;
        s[1][0] += a.y * b.x; s[1][1] += a.y * b.y; s[1][2] += a.y * b.z; s[1][3] += a.y * b.w;
        s[2][0] += a.z * b.x; s[2][1] += a.z * b.y; s[2][2] += a.z * b.z; s[2][3] += a.z * b.w;
        s[3][0] += a.w * b.x; s[3][1] += a.w * b.y; s[3][2] += a.w * b.z; s[3][3] += a.w * b.w;
    }
#pragma unroll
    for (int j = 0; j < 4; j++)
#pragma unroll
        for (int i = 0; i < 4; i++)
            St[(tk * 4 + j) * PAD + tq * 4 + i] = s[i][j];
}

template <int GRP>
__device__ __forceinline__ void softmax_pv(
    float* St, const float* Vs, float* red,
    float* s_m, float* s_l, float* s_al,
    float acc[4][4], int base, int pend, int tid)
{
    __syncthreads();
    int r = tid & 63, sub = tid >> 6;
    float pm = -1e30f;
#pragma unroll
    for (int kk = sub * 16; kk < sub * 16 + 16; kk++) {
        int kidx = base + kk;
        bool in = (GRP == 0) ? (kidx < pend)
                             : ((kidx < REG_N) || (kidx >= pend && kidx < N_TOK));
        float v = St[kk * PAD + r];
        if (in) pm = fmaxf(pm, v);
    }
    red[sub * 64 + r] = pm;
    __syncthreads();
    if (tid < 64) {
        float mt = fmaxf(fmaxf(red[tid], red[64 + tid]),
                         fmaxf(red[128 + tid], red[192 + tid]));
        float mo = s_m[tid];
        float mn2 = fmaxf(mo, mt);
        s_al[tid] = __expf(mo - mn2);
        s_m[tid] = mn2;
    }
    __syncthreads();
    float mnv = s_m[r];
    float ps = 0.f;
#pragma unroll
    for (int kk = sub * 16; kk < sub * 16 + 16; kk++) {
        int kidx = base + kk;
        bool in = (GRP == 0) ? (kidx < pend)
                             : ((kidx < REG_N) || (kidx >= pend && kidx < N_TOK));
        float e = in ? __expf(St[kk * PAD + r] - mnv) : 0.f;
        St[kk * PAD + r] = e;
        ps += e;
    }
    red[sub * 64 + r] = ps;
    __syncthreads();
    if (tid < 64)
        s_l[tid] = s_l[tid] * s_al[tid]
                 + red[tid] + red[64 + tid] + red[128 + tid] + red[192 + tid];
    int tq = tid >> 4, td = tid & 15;
    float al[4];
#pragma unroll
    for (int i = 0; i < 4; i++) al[i] = s_al[tq * 4 + i];
#pragma unroll
    for (int i = 0; i < 4; i++)
#pragma unroll
        for (int j = 0; j < 4; j++)
            acc[i][j] *= al[i];
#pragma unroll 4
    for (int k = 0; k < 64; k++) {
        float4 a = *(const float4*)&St[k * PAD + tq * 4];
        float4 b = *(const float4*)&Vs[k * PAD + td * 4];
        acc[0][0] += a.x * b.x; acc[0][1] += a.x * b.y; acc[0][2] += a.x * b.z; acc[0][3] += a.x * b.w;
        acc[1][0] += a.y * b.x; acc[1][1] += a.y * b.y; acc[1][2] += a.y * b.z; acc[1][3] += a.y * b.w;
        acc[2][0] += a.z * b.x; acc[2][1] += a.z * b.y; acc[2][2] += a.z * b.z; acc[2][3] += a.z * b.w;
        acc[3][0] += a.w * b.x; acc[3][1] += a.w * b.y; acc[3][2] += a.w * b.z; acc[3][3] += a.w * b.w;
    }
}

__global__ __launch_bounds__(256) void flash_kernel(int /*dummy*/)
{
    extern __shared__ float smf[];
    float* Qst = smf;
    float* Kst = Qst + 64 * PAD;
    float* Vs  = Kst + 64 * PAD;
    float* St  = Vs  + 64 * PAD;
    float* red  = St + 64 * PAD;
    float* s_mp = red + 256;
    float* s_lp = s_mp + 64;
    float* s_mn = s_lp + 64;
    float* s_ln = s_mn + 64;
    float* s_al = s_ln + 64;

    int tid = threadIdx.x;
    int h = blockIdx.y, qt = blockIdx.x;
    int qbase = qt * 64;
    int pend = REG_N + g_npos[0];

    {
        int r = tid >> 2, c0 = (tid & 3) * 16;
        int q = qbase + r;
        const float* src = g_qkv + (size_t)q * (3 * CDIM) + h * DH;
#pragma unroll
        for (int d4 = c0; d4 < c0 + 16; d4 += 4) {
            float4 qv = make_float4(0.f, 0.f, 0.f, 0.f);
            if (q < N_TOK) qv = *(const float4*)(src + d4);
            Qst[(d4 + 0) * PAD + r] = qv.x * SCALE;
            Qst[(d4 + 1) * PAD + r] = qv.y * SCALE;
            Qst[(d4 + 2) * PAD + r] = qv.z * SCALE;
            Qst[(d4 + 3) * PAD + r] = qv.w * SCALE;
        }
    }
    if (tid < 64) {
        s_mp[tid] = -1e30f; s_lp[tid] = 0.f;
        s_mn[tid] = -1e30f; s_ln[tid] = 0.f;
    }
    float accp[4][4] = {}, accn[4][4] = {};
    int tq = tid >> 4, tk = tid & 15;

    for (int base = 0; base < N_TOK; base += 64) {
        __syncthreads();
        {
            int r = tid >> 2, c0 = (tid & 3) * 16;
            int kidx = base + r;
            const float* ksrc = g_kp + (size_t)kidx * CDIM + h * DH;
            const float* vsrc = g_vp + (size_t)kidx * CDIM + h * DH;
#pragma unroll
            for (int d4 = c0; d4 < c0 + 16; d4 += 4) {
                float4 kv = make_float4(0.f, 0.f, 0.f, 0.f);
                float4 vv = make_float4(0.f, 0.f, 0.f, 0.f);
                if (kidx < N_TOK) {
                    kv = *(const float4*)(ksrc + d4);
                    vv = *(const float4*)(vsrc + d4);
                }
                Kst[(d4 + 0) * PAD + r] = kv.x;
                Kst[(d4 + 1) * PAD + r] = kv.y;
                Kst[(d4 + 2) * PAD + r] = kv.z;
                Kst[(d4 + 3) * PAD + r] = kv.w;
                *(float4*)&Vs[r * PAD + d4] = vv;
            }
        }
        __syncthreads();

        bool runPos = base < pend;
        bool runNeg = (base < REG_N) || (base + 64 > pend);

        compute_S(Qst, Kst, St, tq, tk);
        if (runPos)
            softmax_pv<0>(St, Vs, red, s_mp, s_lp, s_al, accp, base, pend, tid);
        if (runNeg) {
            if (runPos) { __syncthreads(); compute_S(Qst, Kst, St, tq, tk); }
            softmax_pv<1>(St, Vs, red, s_mn, s_ln, s_al, accn, base, pend, tid);
        }
    }
    __syncthreads();

    int td = tid & 15;
    tq = tid >> 4;
#pragma unroll
    for (int i = 0; i < 4; i++) {
        int r = tq * 4 + i;
        int q = qbase + r;
        if (q >= N_TOK) continue;
        float invlp = 1.f / s_lp[r];
        float invln = 1.f / s_ln[r];
        float vals[4];
#pragma unroll
        for (int j = 0; j < 4; j++) {
            float op = accp[i][j] * invlp;
            float on = accn[i][j] * invln;
            float vv;
            if (q < REG_N) vv = 0.5f * (op + on);
            else vv = g_flag[q - REG_N] ? op : on;
            vals[j] = vv;
        }
        *(float4*)(g_attn + (size_t)q * CDIM + h * DH + td * 4) =
            make_float4(vals[0], vals[1], vals[2], vals[3]);
    }
}

// ---------------- launcher ----------------
extern "C" void kernel_launch(void* const* d_in, const int* in_sizes, int n_in,
                              void* d_out, int out_size)
{
    const float* x = nullptr; const float* ginfo = nullptr;
    const float* wqkv = nullptr; const float* wproj = nullptr;
    const float* bproj = nullptr;
    for (int i = 0; i < n_in; i++) {
        switch (in_sizes[i]) {
            case N_TOK * CDIM:      x = (const float*)d_in[i]; break;
            case 12 * 2 * CDIM:     ginfo = (const float*)d_in[i]; break;
            case CDIM * 3 * CDIM:   wqkv = (const float*)d_in[i]; break;
            case CDIM * CDIM:       wproj = (const float*)d_in[i]; break;
            case CDIM:              bproj = (const float*)d_in[i]; break;
        }
    }
    float* out = (float*)d_out;

    float* qkv;  cudaGetSymbolAddress((void**)&qkv,  g_qkv);
    float* attn; cudaGetSymbolAddress((void**)&attn, g_attn);

    int gsmem = GEMM_SMEM_FLOATS * (int)sizeof(float);  // 69632
    cudaFuncSetAttribute(gemm_mma, cudaFuncAttributeMaxDynamicSharedMemorySize, gsmem);
    int fsmem = (4 * 64 * PAD + 256 + 5 * 64) * (int)sizeof(float);
    cudaFuncSetAttribute(flash_kernel, cudaFuncAttributeMaxDynamicSharedMemorySize, fsmem);

    // [0] QKV GEMM: (2309,1024) @ (1024,3072), tf32 mma x3
    gemm_mma<<<dim3(3 * CDIM / 128, (N_TOK + 127) / 128), 256, gsmem>>>(
        x, wqkv, nullptr, qkv, N_TOK, 3 * CDIM, CDIM);
    // [1] similarity
    sim_kernel<<<N_T, 128>>>(ginfo);
    // [2] minmax + mask + scan
    maskscan_kernel<<<1, 768>>>();
    // [3] gather K
    gatherK_kernel<<<N_TOK, 256>>>(0);
    // [4] gather V
    gatherV_kernel<<<N_TOK, 256>>>(0);
    // [5] flash attention  (ncu -s 5 lands here)
    flash_kernel<<<dim3((N_TOK + 63) / 64, HEADS), 256, fsmem>>>(0);
    // [6] projection GEMM + bias
    gemm_mma<<<dim3(CDIM / 128, (N_TOK + 127) / 128), 256, gsmem>>>(
        attn, wproj, bproj, out, N_TOK, CDIM, CDIM);
}

// round 6
// speedup vs baseline: 1.5381x; 1.3017x over previous
#include <cuda_runtime.h>
#include <cuda_bf16.h>
#include <math.h>
#include <stdint.h>

#define N_TOK 2309
#define N_T   2304
#define CDIM  1024
#define HEADS 16
#define DH    64
#define REG_N 5
#define SCALE 0.125f   // 64^-0.5

// ---------------- device scratch (static, no runtime alloc) ----------------
__device__ float g_qkv[(size_t)N_TOK * 3 * CDIM];   // (n, 3*1024): q|k|v per row
__device__ float g_attn[(size_t)N_TOK * CDIM];      // attention output (orig query order)
__device__ float g_sim[N_T];
__device__ int   g_perm[N_TOK];
__device__ int   g_npos[1];
__device__ unsigned char g_flag[N_T];

// ================= warp-level tf32 MMA GEMM (3xTF32) ==========================
#define GPITCH 136
#define SLAB   32
#define OFF_AH 0
#define OFF_AL (SLAB * GPITCH)
#define OFF_BH (2 * SLAB * GPITCH)
#define OFF_BL (3 * SLAB * GPITCH)
#define GEMM_SMEM_FLOATS (4 * SLAB * GPITCH)

__device__ __forceinline__ float tf32r(float v)
{
    uint32_t u;
    asm("cvt.rna.tf32.f32 %0, %1;" : "=r"(u) : "f"(v));
    return __uint_as_float(u);
}

__device__ __forceinline__ void mma_tf32(float* d, const uint32_t* a, const uint32_t* b)
{
    asm volatile(
        "mma.sync.aligned.m16n8k8.row.col.f32.tf32.tf32.f32 "
        "{%0,%1,%2,%3}, {%4,%5,%6,%7}, {%8,%9}, {%0,%1,%2,%3};"
        : "+f"(d[0]), "+f"(d[1]), "+f"(d[2]), "+f"(d[3])
        : "r"(a[0]), "r"(a[1]), "r"(a[2]), "r"(a[3]), "r"(b[0]), "r"(b[1]));
}

__global__ __launch_bounds__(256) void gemm_mma(
    const float* __restrict__ A, const float* __restrict__ B,
    const float* __restrict__ bias, float* __restrict__ C,
    int M, int N, int K)
{
    extern __shared__ float sm[];
    float* sAh = sm + OFF_AH;
    float* sAl = sm + OFF_AL;
    float* sBh = sm + OFF_BH;
    float* sBl = sm + OFF_BL;

    int tid = threadIdx.x;
    int warp = tid >> 5, lane = tid & 31;
    int g = lane >> 2, t = lane & 3;
    int mw = (warp >> 1) * 32;
    int nw = (warp & 1) * 64;
    int brow = blockIdx.y, bcol = blockIdx.x;

    int aRow = tid >> 1;
    int aHalf = (tid & 1) * 16;
    int aRowG = brow * 128 + aRow;
    bool aok = aRowG < M;
    const float* aptr = A + (size_t)aRowG * K + aHalf;
    int bK = tid >> 3;
    int bN0 = (tid & 7) * 16;
    const float* bptr = B + (size_t)bK * N + bcol * 128 + bN0;

    float c[64];
#pragma unroll
    for (int i = 0; i < 64; i++) c[i] = 0.f;

    int nslab = K / SLAB;
    for (int s = 0; s < nslab; s++) {
        if (s) __syncthreads();
#pragma unroll
        for (int j = 0; j < 4; j++) {
            float4 v = make_float4(0.f, 0.f, 0.f, 0.f);
            if (aok) v = *(const float4*)(aptr + s * SLAB + j * 4);
            int k0 = aHalf + j * 4;
            float hx = tf32r(v.x), hy = tf32r(v.y), hz = tf32r(v.z), hw = tf32r(v.w);
            sAh[(k0 + 0) * GPITCH + aRow] = hx;
            sAh[(k0 + 1) * GPITCH + aRow] = hy;
            sAh[(k0 + 2) * GPITCH + aRow] = hz;
            sAh[(k0 + 3) * GPITCH + aRow] = hw;
            sAl[(k0 + 0) * GPITCH + aRow] = tf32r(v.x - hx);
            sAl[(k0 + 1) * GPITCH + aRow] = tf32r(v.y - hy);
            sAl[(k0 + 2) * GPITCH + aRow] = tf32r(v.z - hz);
            sAl[(k0 + 3) * GPITCH + aRow] = tf32r(v.w - hw);
        }
#pragma unroll
        for (int j = 0; j < 4; j++) {
            float4 v = *(const float4*)(bptr + (size_t)s * SLAB * N + j * 4);
            float4 hi, lo;
            hi.x = tf32r(v.x); lo.x = tf32r(v.x - hi.x);
            hi.y = tf32r(v.y); lo.y = tf32r(v.y - hi.y);
            hi.z = tf32r(v.z); lo.z = tf32r(v.z - hi.z);
            hi.w = tf32r(v.w); lo.w = tf32r(v.w - hi.w);
            *(float4*)&sBh[bK * GPITCH + bN0 + j * 4] = hi;
            *(float4*)&sBl[bK * GPITCH + bN0 + j * 4] = lo;
        }
        __syncthreads();
#pragma unroll
        for (int kk = 0; kk < SLAB; kk += 8) {
            uint32_t ah[2][4], al[2][4];
#pragma unroll
            for (int am = 0; am < 2; am++) {
                int m0 = mw + am * 16 + g;
#pragma unroll
                for (int rr = 0; rr < 4; rr++) {
                    int k = kk + t + ((rr >> 1) << 2);
                    int m = m0 + ((rr & 1) << 3);
                    ah[am][rr] = __float_as_uint(sAh[k * GPITCH + m]);
                    al[am][rr] = __float_as_uint(sAl[k * GPITCH + m]);
                }
            }
#pragma unroll
            for (int an = 0; an < 8; an++) {
                int n = nw + an * 8 + g;
                uint32_t bh[2], bl[2];
#pragma unroll
                for (int rr = 0; rr < 2; rr++) {
                    int k = kk + t + rr * 4;
                    bh[rr] = __float_as_uint(sBh[k * GPITCH + n]);
                    bl[rr] = __float_as_uint(sBl[k * GPITCH + n]);
                }
#pragma unroll
                for (int am = 0; am < 2; am++) {
                    float* cc = &c[(am * 8 + an) * 4];
                    mma_tf32(cc, ah[am], bh);
                    mma_tf32(cc, al[am], bh);
                    mma_tf32(cc, ah[am], bl);
                }
            }
        }
    }

#pragma unroll
    for (int am = 0; am < 2; am++) {
#pragma unroll
        for (int an = 0; an < 8; an++) {
            float* cc = &c[(am * 8 + an) * 4];
            int row0 = brow * 128 + mw + am * 16 + g;
            int col = bcol * 128 + nw + an * 8 + 2 * t;
            float bx = 0.f, by = 0.f;
            if (bias) { bx = bias[col]; by = bias[col + 1]; }
            if (row0 < M) {
                float2 o; o.x = cc[0] + bx; o.y = cc[1] + by;
                *(float2*)(C + (size_t)row0 * N + col) = o;
            }
            if (row0 + 8 < M) {
                float2 o; o.x = cc[2] + bx; o.y = cc[3] + by;
                *(float2*)(C + (size_t)(row0 + 8) * N + col) = o;
            }
        }
    }
}

// ---------------- similarity ----------------
__global__ void sim_kernel(const float* __restrict__ g_info)
{
    int t = blockIdx.x;
    int lane = threadIdx.x & 31, warp = threadIdx.x >> 5;
    __shared__ float wacc[4];
    const float* qrow = g_qkv + (size_t)(t + REG_N) * (3 * CDIM);
    float local = 0.f;
    for (int h = warp; h < HEADS; h += 4) {
        float q0 = qrow[h * DH + lane];
        float q1 = qrow[h * DH + lane + 32];
        float g0 = g_info[h * DH + lane];
        float g1 = g_info[h * DH + lane + 32];
        float d = q0 * g0 + q1 * g1;
        float nq = q0 * q0 + q1 * q1;
        float ng = g0 * g0 + g1 * g1;
#pragma unroll
        for (int o = 16; o > 0; o >>= 1) {
            d  += __shfl_xor_sync(0xffffffffu, d, o);
            nq += __shfl_xor_sync(0xffffffffu, nq, o);
            ng += __shfl_xor_sync(0xffffffffu, ng, o);
        }
        if (lane == 0) local += d / (sqrtf(nq) * sqrtf(ng));
    }
    if (lane == 0) wacc[warp] = local;
    __syncthreads();
    if (threadIdx.x == 0)
        g_sim[t] = (wacc[0] + wacc[1] + wacc[2] + wacc[3]) * (1.0f / 16.0f);
}

// ---------------- minmax + threshold + scan -> key permutation --------------
__global__ void maskscan_kernel()
{
    int tid = threadIdx.x;
    int lane = tid & 31, warp = tid >> 5;
    int t0 = tid * 3;
    float v0 = g_sim[t0], v1 = g_sim[t0 + 1], v2 = g_sim[t0 + 2];
    float mn = fminf(v0, fminf(v1, v2));
    float mx = fmaxf(v0, fmaxf(v1, v2));
#pragma unroll
    for (int o = 16; o > 0; o >>= 1) {
        mn = fminf(mn, __shfl_xor_sync(0xffffffffu, mn, o));
        mx = fmaxf(mx, __shfl_xor_sync(0xffffffffu, mx, o));
    }
    __shared__ float smn[24], smx[24];
    __shared__ float s_bmn, s_bmx;
    if (lane == 0) { smn[warp] = mn; smx[warp] = mx; }
    __syncthreads();
    if (tid == 0) {
        float a = smn[0], b = smx[0];
        for (int w = 1; w < 24; w++) { a = fminf(a, smn[w]); b = fmaxf(b, smx[w]); }
        s_bmn = a; s_bmx = b;
    }
    __syncthreads();
    float bmn = s_bmn;
    float inv = 1.0f / (s_bmx - bmn);
    int f[3]; int c = 0;
    f[0] = ((v0 - bmn) * inv > 0.9f) ? 1 : 0;
    f[1] = ((v1 - bmn) * inv > 0.9f) ? 1 : 0;
    f[2] = ((v2 - bmn) * inv > 0.9f) ? 1 : 0;
#pragma unroll
    for (int e = 0; e < 3; e++) {
        c += f[e];
        g_flag[t0 + e] = (unsigned char)f[e];
    }
    int incl = c;
#pragma unroll
    for (int o = 1; o < 32; o <<= 1) {
        int v = __shfl_up_sync(0xffffffffu, incl, o);
        if (lane >= o) incl += v;
    }
    __shared__ int wsum[24];
    __shared__ int s_npos;
    if (lane == 31) wsum[warp] = incl;
    __syncthreads();
    if (tid == 0) {
        int acc = 0;
        for (int w = 0; w < 24; w++) { int v = wsum[w]; wsum[w] = acc; acc += v; }
        s_npos = acc;
        g_npos[0] = acc;
        for (int i = 0; i < REG_N; i++) g_perm[i] = i;
    }
    __syncthreads();
    int excl = incl - c + wsum[warp];
    int npos = s_npos;
    int pp = excl;
#pragma unroll
    for (int e = 0; e < 3; e++) {
        int t = t0 + e;
        if (f[e]) { g_perm[REG_N + pp] = t + REG_N; pp++; }
        else      { g_perm[REG_N + npos + (t - pp)] = t + REG_N; }
    }
}

// ================== tensor-core flash attention (bf16x3) =====================
__device__ __forceinline__ float bf16rt(float x)
{
    __nv_bfloat16 h = __float2bfloat16(x);
    return __bfloat162float(h);
}
__device__ __forceinline__ uint32_t pack2(float lo, float hi)
{
    uint32_t r;
    asm("cvt.rn.bf16x2.f32 %0, %1, %2;" : "=r"(r) : "f"(hi), "f"(lo));
    return r;
}
__device__ __forceinline__ void mma16816(float* d, const uint32_t* a, const uint32_t* b)
{
    asm volatile(
        "mma.sync.aligned.m16n8k16.row.col.f32.bf16.bf16.f32 "
        "{%0,%1,%2,%3},{%4,%5,%6,%7},{%8,%9},{%0,%1,%2,%3};"
        : "+f"(d[0]), "+f"(d[1]), "+f"(d[2]), "+f"(d[3])
        : "r"(a[0]), "r"(a[1]), "r"(a[2]), "r"(a[3]), "r"(b[0]), "r"(b[1]));
}

// smem byte offsets
#define F_KH   0
#define F_KL   9216
#define F_VH   18432
#define F_VL   27648
#define F_PERM 36864
#define F_RED0 37120
#define F_RED1 37376
#define F_MP   37632
#define F_LP   37888
#define F_MN   38144
#define F_LN   38400
#define F_AL   38656
#define F_TOTAL 38912

template <int GRP>
__device__ __forceinline__ void group_pass(
    float sacc[4][4], float o[8][4],
    const uint32_t* VHu, const uint32_t* VLu,
    float* red0, float* red1, float* s_m, float* s_l, float* s_al,
    int base, int pend, int tid, int g, int t, int mi, int hf)
{
    int r0 = mi * 16 + g, r1 = r0 + 8;
    float pm0 = -1e30f, pm1 = -1e30f;
#pragma unroll
    for (int nj = 0; nj < 4; nj++) {
        int kc = base + (hf * 4 + nj) * 8 + 2 * t;
        bool in0 = (GRP == 0) ? (kc < pend)
                              : ((kc < REG_N) || (kc >= pend && kc < N_TOK));
        bool in1 = (GRP == 0) ? (kc + 1 < pend)
                              : ((kc + 1 < REG_N) || (kc + 1 >= pend && kc + 1 < N_TOK));
        if (in0) { pm0 = fmaxf(pm0, sacc[nj][0]); pm1 = fmaxf(pm1, sacc[nj][2]); }
        if (in1) { pm0 = fmaxf(pm0, sacc[nj][1]); pm1 = fmaxf(pm1, sacc[nj][3]); }
    }
    pm0 = fmaxf(pm0, __shfl_xor_sync(0xffffffffu, pm0, 1));
    pm0 = fmaxf(pm0, __shfl_xor_sync(0xffffffffu, pm0, 2));
    pm1 = fmaxf(pm1, __shfl_xor_sync(0xffffffffu, pm1, 1));
    pm1 = fmaxf(pm1, __shfl_xor_sync(0xffffffffu, pm1, 2));
    if (t == 0) {
        float* rd = hf ? red1 : red0;
        rd[r0] = pm0; rd[r1] = pm1;
    }
    __syncthreads();
    if (tid < 64) {
        float mt = fmaxf(red0[tid], red1[tid]);
        float mo = s_m[tid];
        float mn2 = fmaxf(mo, mt);
        s_al[tid] = __expf(mo - mn2);
        s_m[tid] = mn2;
    }
    __syncthreads();
    float m0 = s_m[r0], m1 = s_m[r1];
    float p[4][4];
    float ps0 = 0.f, ps1 = 0.f;
#pragma unroll
    for (int nj = 0; nj < 4; nj++) {
        int kc = base + (hf * 4 + nj) * 8 + 2 * t;
        bool in0 = (GRP == 0) ? (kc < pend)
                              : ((kc < REG_N) || (kc >= pend && kc < N_TOK));
        bool in1 = (GRP == 0) ? (kc + 1 < pend)
                              : ((kc + 1 < REG_N) || (kc + 1 >= pend && kc + 1 < N_TOK));
        p[nj][0] = in0 ? __expf(sacc[nj][0] - m0) : 0.f;
        p[nj][1] = in1 ? __expf(sacc[nj][1] - m0) : 0.f;
        p[nj][2] = in0 ? __expf(sacc[nj][2] - m1) : 0.f;
        p[nj][3] = in1 ? __expf(sacc[nj][3] - m1) : 0.f;
        ps0 += p[nj][0] + p[nj][1];
        ps1 += p[nj][2] + p[nj][3];
    }
    ps0 += __shfl_xor_sync(0xffffffffu, ps0, 1);
    ps0 += __shfl_xor_sync(0xffffffffu, ps0, 2);
    ps1 += __shfl_xor_sync(0xffffffffu, ps1, 1);
    ps1 += __shfl_xor_sync(0xffffffffu, ps1, 2);
    if (t == 0) {
        float* rd = hf ? red1 : red0;
        rd[r0] = ps0; rd[r1] = ps1;
    }
    __syncthreads();
    if (tid < 64)
        s_l[tid] = s_l[tid] * s_al[tid] + red0[tid] + red1[tid];
    // rescale O accumulators
    float al0 = s_al[r0], al1 = s_al[r1];
#pragma unroll
    for (int nd = 0; nd < 8; nd++) {
        o[nd][0] *= al0; o[nd][1] *= al0;
        o[nd][2] *= al1; o[nd][3] *= al1;
    }
    // pack P into A fragments (hi/lo bf16)
    uint32_t ah[2][4], alo[2][4];
#pragma unroll
    for (int ks = 0; ks < 2; ks++) {
        float h00 = bf16rt(p[2 * ks][0]),     h01 = bf16rt(p[2 * ks][1]);
        float h02 = bf16rt(p[2 * ks][2]),     h03 = bf16rt(p[2 * ks][3]);
        float h10 = bf16rt(p[2 * ks + 1][0]), h11 = bf16rt(p[2 * ks + 1][1]);
        float h12 = bf16rt(p[2 * ks + 1][2]), h13 = bf16rt(p[2 * ks + 1][3]);
        ah[ks][0] = pack2(h00, h01);
        ah[ks][1] = pack2(h02, h03);
        ah[ks][2] = pack2(h10, h11);
        ah[ks][3] = pack2(h12, h13);
        alo[ks][0] = pack2(p[2 * ks][0] - h00,     p[2 * ks][1] - h01);
        alo[ks][1] = pack2(p[2 * ks][2] - h02,     p[2 * ks][3] - h03);
        alo[ks][2] = pack2(p[2 * ks + 1][0] - h10, p[2 * ks + 1][1] - h11);
        alo[ks][3] = pack2(p[2 * ks + 1][2] - h12, p[2 * ks + 1][3] - h13);
    }
    // PV
#pragma unroll
    for (int nd = 0; nd < 8; nd++) {
        int db = (nd * 8 + g) * 36 + hf * 16;
#pragma unroll
        for (int ks = 0; ks < 2; ks++) {
            uint32_t bh[2], bl[2];
            bh[0] = VHu[db + ks * 8 + t];
            bh[1] = VHu[db + ks * 8 + 4 + t];
            bl[0] = VLu[db + ks * 8 + t];
            bl[1] = VLu[db + ks * 8 + 4 + t];
            mma16816(o[nd], ah[ks], bh);
            mma16816(o[nd], alo[ks], bh);
            mma16816(o[nd], ah[ks], bl);
        }
    }
    __syncthreads();
}

__global__ __launch_bounds__(256) void flash_kernel(int /*dummy*/)
{
    extern __shared__ char smc[];
    uint32_t* KH = (uint32_t*)(smc + F_KH);
    uint32_t* KL = (uint32_t*)(smc + F_KL);
    __nv_bfloat16* VHb = (__nv_bfloat16*)(smc + F_VH);
    __nv_bfloat16* VLb = (__nv_bfloat16*)(smc + F_VL);
    const uint32_t* VHu = (const uint32_t*)(smc + F_VH);
    const uint32_t* VLu = (const uint32_t*)(smc + F_VL);
    int* permS = (int*)(smc + F_PERM);
    float* red0 = (float*)(smc + F_RED0);
    float* red1 = (float*)(smc + F_RED1);
    float* s_mp = (float*)(smc + F_MP);
    float* s_lp = (float*)(smc + F_LP);
    float* s_mn = (float*)(smc + F_MN);
    float* s_ln = (float*)(smc + F_LN);
    float* s_al = (float*)(smc + F_AL);

    int tid = threadIdx.x;
    int warp = tid >> 5, lane = tid & 31;
    int g = lane >> 2, t = lane & 3;
    int mi = warp >> 1, hf = warp & 1;
    int h = blockIdx.y, qt = blockIdx.x;
    int qbase = qt * 64;
    int pend = REG_N + g_npos[0];

    // ---- Q fragments (hi/lo bf16), scaled ----
    uint32_t Qh[4][4], Ql[4][4];
    {
        int r0g = qbase + mi * 16 + g;
        int r1g = r0g + 8;
        bool ok0 = r0g < N_TOK, ok1 = r1g < N_TOK;
        const float* q0p = g_qkv + (size_t)r0g * (3 * CDIM) + h * DH;
        const float* q1p = g_qkv + (size_t)r1g * (3 * CDIM) + h * DH;
#pragma unroll
        for (int ks = 0; ks < 4; ks++) {
            int d0 = ks * 16 + 2 * t;
            float2 x0 = ok0 ? *(const float2*)(q0p + d0) : make_float2(0.f, 0.f);
            float2 x1 = ok1 ? *(const float2*)(q1p + d0) : make_float2(0.f, 0.f);
            float2 x2 = ok0 ? *(const float2*)(q0p + d0 + 8) : make_float2(0.f, 0.f);
            float2 x3 = ok1 ? *(const float2*)(q1p + d0 + 8) : make_float2(0.f, 0.f);
            x0.x *= SCALE; x0.y *= SCALE; x1.x *= SCALE; x1.y *= SCALE;
            x2.x *= SCALE; x2.y *= SCALE; x3.x *= SCALE; x3.y *= SCALE;
            float h0x = bf16rt(x0.x), h0y = bf16rt(x0.y);
            float h1x = bf16rt(x1.x), h1y = bf16rt(x1.y);
            float h2x = bf16rt(x2.x), h2y = bf16rt(x2.y);
            float h3x = bf16rt(x3.x), h3y = bf16rt(x3.y);
            Qh[ks][0] = pack2(h0x, h0y); Ql[ks][0] = pack2(x0.x - h0x, x0.y - h0y);
            Qh[ks][1] = pack2(h1x, h1y); Ql[ks][1] = pack2(x1.x - h1x, x1.y - h1y);
            Qh[ks][2] = pack2(h2x, h2y); Ql[ks][2] = pack2(x2.x - h2x, x2.y - h2y);
            Qh[ks][3] = pack2(h3x, h3y); Ql[ks][3] = pack2(x3.x - h3x, x3.y - h3y);
        }
    }
    if (tid < 64) {
        s_mp[tid] = -1e30f; s_lp[tid] = 0.f;
        s_mn[tid] = -1e30f; s_ln[tid] = 0.f;
    }
    float o[2][8][4];
#pragma unroll
    for (int gi = 0; gi < 2; gi++)
#pragma unroll
        for (int nd = 0; nd < 8; nd++)
#pragma unroll
            for (int e = 0; e < 4; e++) o[gi][nd][e] = 0.f;

    for (int base = 0; base < N_TOK; base += 64) {
        __syncthreads();
        if (tid < 64) {
            int idx = base + tid;
            permS[tid] = (idx < N_TOK) ? g_perm[idx] : 0;
        }
        __syncthreads();
        // ---- load K / V tile into bf16 hi/lo smem ----
        {
            int key = tid >> 2, c0 = (tid & 3) * 16;
            int kidx = base + key;
            bool kok = kidx < N_TOK;
            const float* kr = g_qkv + (size_t)permS[key] * (3 * CDIM) + CDIM + h * DH + c0;
            const float* vr = kr + CDIM;
#pragma unroll
            for (int j = 0; j < 4; j++) {
                float4 kv = kok ? *(const float4*)(kr + j * 4) : make_float4(0.f, 0.f, 0.f, 0.f);
                float4 vv = kok ? *(const float4*)(vr + j * 4) : make_float4(0.f, 0.f, 0.f, 0.f);
                int dp = (c0 >> 1) + j * 2;
                float hx = bf16rt(kv.x), hy = bf16rt(kv.y);
                float hz = bf16rt(kv.z), hw = bf16rt(kv.w);
                KH[key * 36 + dp]     = pack2(hx, hy);
                KH[key * 36 + dp + 1] = pack2(hz, hw);
                KL[key * 36 + dp]     = pack2(kv.x - hx, kv.y - hy);
                KL[key * 36 + dp + 1] = pack2(kv.z - hz, kv.w - hw);
                int d = c0 + j * 4;
                float vhx = bf16rt(vv.x), vhy = bf16rt(vv.y);
                float vhz = bf16rt(vv.z), vhw = bf16rt(vv.w);
                VHb[(d + 0) * 72 + key] = __float2bfloat16(vv.x);
                VHb[(d + 1) * 72 + key] = __float2bfloat16(vv.y);
                VHb[(d + 2) * 72 + key] = __float2bfloat16(vv.z);
                VHb[(d + 3) * 72 + key] = __float2bfloat16(vv.w);
                VLb[(d + 0) * 72 + key] = __float2bfloat16(vv.x - vhx);
                VLb[(d + 1) * 72 + key] = __float2bfloat16(vv.y - vhy);
                VLb[(d + 2) * 72 + key] = __float2bfloat16(vv.z - vhz);
                VLb[(d + 3) * 72 + key] = __float2bfloat16(vv.w - vhw);
            }
        }
        __syncthreads();
        // ---- S = Q @ K^T (bf16x3) ----
        float sacc[4][4];
#pragma unroll
        for (int nj = 0; nj < 4; nj++)
#pragma unroll
            for (int e = 0; e < 4; e++) sacc[nj][e] = 0.f;
#pragma unroll
        for (int nj = 0; nj < 4; nj++) {
            int keyb = ((hf * 4 + nj) * 8 + g) * 36;
#pragma unroll
            for (int ks = 0; ks < 4; ks++) {
                uint32_t bh[2], bl[2];
                bh[0] = KH[keyb + ks * 8 + t];
                bh[1] = KH[keyb + ks * 8 + 4 + t];
                bl[0] = KL[keyb + ks * 8 + t];
                bl[1] = KL[keyb + ks * 8 + 4 + t];
                mma16816(sacc[nj], Qh[ks], bh);
                mma16816(sacc[nj], Ql[ks], bh);
                mma16816(sacc[nj], Qh[ks], bl);
            }
        }
        bool runPos = base < pend;
        bool runNeg = (base < REG_N) || (base + 64 > pend);
        if (runPos)
            group_pass<0>(sacc, o[0], VHu, VLu, red0, red1,
                          s_mp, s_lp, s_al, base, pend, tid, g, t, mi, hf);
        if (runNeg)
            group_pass<1>(sacc, o[1], VHu, VLu, red0, red1,
                          s_mn, s_ln, s_al, base, pend, tid, g, t, mi, hf);
    }
    __syncthreads();

    // ---- epilogue: combine warp halves, normalize, pos/neg select ----
    float* PB = (float*)smc;             // [64][72] pos partial
    float* NB = PB + 64 * 72;            // [64][72] neg partial
    int r0 = mi * 16 + g, r1 = r0 + 8;
    if (hf == 1) {
#pragma unroll
        for (int nd = 0; nd < 8; nd++) {
            int c = nd * 8 + 2 * t;
            *(float2*)&PB[r0 * 72 + c] = make_float2(o[0][nd][0], o[0][nd][1]);
            *(float2*)&PB[r1 * 72 + c] = make_float2(o[0][nd][2], o[0][nd][3]);
            *(float2*)&NB[r0 * 72 + c] = make_float2(o[1][nd][0], o[1][nd][1]);
            *(float2*)&NB[r1 * 72 + c] = make_float2(o[1][nd][2], o[1][nd][3]);
        }
    }
    __syncthreads();
    if (hf == 0) {
        int q0 = qbase + r0, q1 = qbase + r1;
        float invlp0 = 1.f / s_lp[r0], invlp1 = 1.f / s_lp[r1];
        float invln0 = 1.f / s_ln[r0], invln1 = 1.f / s_ln[r1];
        bool reg0 = q0 < REG_N, reg1 = q1 < REG_N;
        float fl0 = (q0 >= REG_N && q0 < N_TOK) ? (g_flag[q0 - REG_N] ? 1.f : 0.f) : 0.f;
        float fl1 = (q1 >= REG_N && q1 < N_TOK) ? (g_flag[q1 - REG_N] ? 1.f : 0.f) : 0.f;
#pragma unroll
        for (int nd = 0; nd < 8; nd++) {
            int c = nd * 8 + 2 * t;
            float2 pp0 = *(float2*)&PB[r0 * 72 + c];
            float2 pp1 = *(float2*)&PB[r1 * 72 + c];
            float2 nn0 = *(float2*)&NB[r0 * 72 + c];
            float2 nn1 = *(float2*)&NB[r1 * 72 + c];
            float opx = (o[0][nd][0] + pp0.x) * invlp0;
            float opy = (o[0][nd][1] + pp0.y) * invlp0;
            float onx = (o[1][nd][0] + nn0.x) * invln0;
            float ony = (o[1][nd][1] + nn0.y) * invln0;
            float vx, vy;
            if (reg0) { vx = 0.5f * (opx + onx); vy = 0.5f * (opy + ony); }
            else      { vx = fl0 ? opx : onx;    vy = fl0 ? opy : ony; }
            if (q0 < N_TOK)
                *(float2*)(g_attn + (size_t)q0 * CDIM + h * DH + c) = make_float2(vx, vy);
            float opx1 = (o[0][nd][2] + pp1.x) * invlp1;
            float opy1 = (o[0][nd][3] + pp1.y) * invlp1;
            float onx1 = (o[1][nd][2] + nn1.x) * invln1;
            float ony1 = (o[1][nd][3] + nn1.y) * invln1;
            float wx, wy;
            if (reg1) { wx = 0.5f * (opx1 + onx1); wy = 0.5f * (opy1 + ony1); }
            else      { wx = fl1 ? opx1 : onx1;    wy = fl1 ? opy1 : ony1; }
            if (q1 < N_TOK)
                *(float2*)(g_attn + (size_t)q1 * CDIM + h * DH + c) = make_float2(wx, wy);
        }
    }
}

// ---------------- launcher ----------------
extern "C" void kernel_launch(void* const* d_in, const int* in_sizes, int n_in,
                              void* d_out, int out_size)
{
    const float* x = nullptr; const float* ginfo = nullptr;
    const float* wqkv = nullptr; const float* wproj = nullptr;
    const float* bproj = nullptr;
    for (int i = 0; i < n_in; i++) {
        switch (in_sizes[i]) {
            case N_TOK * CDIM:      x = (const float*)d_in[i]; break;
            case 12 * 2 * CDIM:     ginfo = (const float*)d_in[i]; break;
            case CDIM * 3 * CDIM:   wqkv = (const float*)d_in[i]; break;
            case CDIM * CDIM:       wproj = (const float*)d_in[i]; break;
            case CDIM:              bproj = (const float*)d_in[i]; break;
        }
    }
    float* out = (float*)d_out;

    float* qkv;  cudaGetSymbolAddress((void**)&qkv,  g_qkv);
    float* attn; cudaGetSymbolAddress((void**)&attn, g_attn);

    int gsmem = GEMM_SMEM_FLOATS * (int)sizeof(float);
    cudaFuncSetAttribute(gemm_mma, cudaFuncAttributeMaxDynamicSharedMemorySize, gsmem);
    cudaFuncSetAttribute(flash_kernel, cudaFuncAttributeMaxDynamicSharedMemorySize, F_TOTAL);

    // [1] QKV GEMM (tf32 mma x3)
    gemm_mma<<<dim3(3 * CDIM / 128, (N_TOK + 127) / 128), 256, gsmem>>>(
        x, wqkv, nullptr, qkv, N_TOK, 3 * CDIM, CDIM);
    // [2] similarity
    sim_kernel<<<N_T, 128>>>(ginfo);
    // [3] minmax + mask + scan
    maskscan_kernel<<<1, 768>>>();
    // [4] flash attention (tensor core, perm-indexed)  <- profiled launch
    flash_kernel<<<dim3((N_TOK + 63) / 64, HEADS), 256, F_TOTAL>>>(0);
    // [5] projection GEMM + bias
    gemm_mma<<<dim3(CDIM / 128, (N_TOK + 127) / 128), 256, gsmem>>>(
        attn, wproj, bproj, out, N_TOK, CDIM, CDIM);
}